// round 2
// baseline (speedup 1.0000x reference)
#include <cuda_runtime.h>
#include <cstdint>
#include <math.h>

// ---------------- problem constants ----------------
#define HIDDEN 2048
#define NHEADS 32
#define NKV    8
#define HD     64
#define KVREP  (NHEADS / NKV)
#define INTER  8192
#define BATCH  2
#define QLEN   2048
#define KLEN   2048
#define MROWS  (BATCH * QLEN)   // 4096

// ---------------- scratch (static device allocations) ----------------
__device__ float g_normed [(size_t)MROWS * HIDDEN];
__device__ float g_q      [(size_t)MROWS * HIDDEN];
__device__ float g_attn   [(size_t)MROWS * HIDDEN];
__device__ float g_h2     [(size_t)MROWS * HIDDEN];
__device__ float g_normed2[(size_t)MROWS * HIDDEN];
__device__ float g_gate   [(size_t)MROWS * INTER];
__device__ float g_up     [(size_t)MROWS * INTER];

// ---------------- helpers ----------------
__device__ __forceinline__ float to_tf32(float x) {
    uint32_t u;
    asm("cvt.rna.tf32.f32 %0, %1;" : "=r"(u) : "f"(x));
    return __uint_as_float(u);
}

__device__ __forceinline__ void mma_tf32(float (&d)[4], const uint32_t (&a)[4],
                                         const uint32_t (&b)[2]) {
    asm volatile(
        "mma.sync.aligned.m16n8k8.row.col.f32.tf32.tf32.f32 "
        "{%0,%1,%2,%3}, {%4,%5,%6,%7}, {%8,%9}, {%0,%1,%2,%3};\n"
        : "+f"(d[0]), "+f"(d[1]), "+f"(d[2]), "+f"(d[3])
        : "r"(a[0]), "r"(a[1]), "r"(a[2]), "r"(a[3]), "r"(b[0]), "r"(b[1]));
}

// ---------------- RMSNorm ----------------
__global__ void rmsnorm_kernel(const float* __restrict__ x,
                               const float* __restrict__ w,
                               float* __restrict__ out) {
    const int row = blockIdx.x;
    const float* xr = x + (size_t)row * HIDDEN;
    float* orow = out + (size_t)row * HIDDEN;
    float s = 0.f;
    for (int i = threadIdx.x; i < HIDDEN; i += blockDim.x) {
        float v = xr[i];
        s += v * v;
    }
    __shared__ float red[32];
    #pragma unroll
    for (int o = 16; o; o >>= 1) s += __shfl_xor_sync(0xffffffffu, s, o);
    if ((threadIdx.x & 31) == 0) red[threadIdx.x >> 5] = s;
    __syncthreads();
    if (threadIdx.x < 32) {
        float v = (threadIdx.x < (blockDim.x >> 5)) ? red[threadIdx.x] : 0.f;
        #pragma unroll
        for (int o = 16; o; o >>= 1) v += __shfl_xor_sync(0xffffffffu, v, o);
        if (threadIdx.x == 0) red[0] = v;
    }
    __syncthreads();
    const float inv = rsqrtf(red[0] / (float)HIDDEN + 1e-5f);
    for (int i = threadIdx.x; i < HIDDEN; i += blockDim.x)
        orow[i] = xr[i] * inv * w[i];
}

// ---------------- tf32 GEMM: C = A(M,K) @ B(N,K)^T (+ Res) ----------------
// CTA tile 128x128x32, 8 warps, warp tile 64x32 of m16n8k8.
__global__ void __launch_bounds__(256, 2) gemm_tf32(
    const float* __restrict__ A, const float* __restrict__ B,
    const float* __restrict__ Res, float* __restrict__ C,
    int M, int N, int K) {
    constexpr int BK = 32;
    constexpr int LDA = BK + 4;  // pad -> conflict-free fragment loads
    __shared__ float As[128 * LDA];
    __shared__ float Bs[128 * LDA];

    const int tid = threadIdx.x;
    const int warp = tid >> 5, lane = tid & 31;
    const int wm = warp >> 2, wn = warp & 3;
    const int gid = lane >> 2, tig = lane & 3;
    const int m0 = blockIdx.y * 128, n0 = blockIdx.x * 128;

    float acc[4][4][4];
    #pragma unroll
    for (int mt = 0; mt < 4; mt++)
        #pragma unroll
        for (int nt = 0; nt < 4; nt++)
            #pragma unroll
            for (int i = 0; i < 4; i++) acc[mt][nt][i] = 0.f;

    const float* Ag = A + (size_t)m0 * K;
    const float* Bg = B + (size_t)n0 * K;

    for (int k0 = 0; k0 < K; k0 += BK) {
        #pragma unroll
        for (int i = 0; i < 4; i++) {
            int idx = tid + 256 * i;
            int r = idx >> 3, q = (idx & 7) << 2;
            float4 va = *reinterpret_cast<const float4*>(Ag + (size_t)r * K + k0 + q);
            float* da = As + r * LDA + q;
            da[0] = to_tf32(va.x); da[1] = to_tf32(va.y);
            da[2] = to_tf32(va.z); da[3] = to_tf32(va.w);
            float4 vb = *reinterpret_cast<const float4*>(Bg + (size_t)r * K + k0 + q);
            float* db = Bs + r * LDA + q;
            db[0] = to_tf32(vb.x); db[1] = to_tf32(vb.y);
            db[2] = to_tf32(vb.z); db[3] = to_tf32(vb.w);
        }
        __syncthreads();
        #pragma unroll
        for (int ks = 0; ks < BK; ks += 8) {
            uint32_t af[4][4], bf[4][2];
            #pragma unroll
            for (int mt = 0; mt < 4; mt++) {
                const uint32_t* p = reinterpret_cast<const uint32_t*>(
                    As + (wm * 64 + mt * 16 + gid) * LDA + ks + tig);
                af[mt][0] = p[0];
                af[mt][1] = p[8 * LDA];
                af[mt][2] = p[4];
                af[mt][3] = p[8 * LDA + 4];
            }
            #pragma unroll
            for (int nt = 0; nt < 4; nt++) {
                const uint32_t* p = reinterpret_cast<const uint32_t*>(
                    Bs + (wn * 32 + nt * 8 + gid) * LDA + ks + tig);
                bf[nt][0] = p[0];
                bf[nt][1] = p[4];
            }
            #pragma unroll
            for (int mt = 0; mt < 4; mt++)
                #pragma unroll
                for (int nt = 0; nt < 4; nt++)
                    mma_tf32(acc[mt][nt], af[mt], bf[nt]);
        }
        __syncthreads();
    }

    #pragma unroll
    for (int mt = 0; mt < 4; mt++) {
        int r = m0 + wm * 64 + mt * 16 + gid;
        #pragma unroll
        for (int nt = 0; nt < 4; nt++) {
            int c = n0 + wn * 32 + nt * 8 + tig * 2;
            size_t o0 = (size_t)r * N + c;
            size_t o1 = o0 + (size_t)8 * N;
            float2 v0 = make_float2(acc[mt][nt][0], acc[mt][nt][1]);
            float2 v1 = make_float2(acc[mt][nt][2], acc[mt][nt][3]);
            if (Res) {
                float2 r0 = *reinterpret_cast<const float2*>(Res + o0);
                float2 r1 = *reinterpret_cast<const float2*>(Res + o1);
                v0.x += r0.x; v0.y += r0.y;
                v1.x += r1.x; v1.y += r1.y;
            }
            *reinterpret_cast<float2*>(C + o0) = v0;
            *reinterpret_cast<float2*>(C + o1) = v1;
        }
    }
}

// ---------------- flash attention (fp32, 64x64 tiles) ----------------
// grid (QLEN/64, NHEADS, BATCH), 256 threads. thread -> (row = tid/4, sub = tid%4)
// score/out columns per thread: 4*j + sub (conflict-free with row stride 68).
constexpr int ATTN_TILE = 64 * 68;  // floats per smem tile
constexpr int ATTN_SMEM = 4 * ATTN_TILE * (int)sizeof(float);  // 69632 B

__global__ void __launch_bounds__(256) attn_kernel(
    const float* __restrict__ Q, const float* __restrict__ Kg,
    const float* __restrict__ Vg, float* __restrict__ O,
    const int* __restrict__ cu_q, const int* __restrict__ cu_k, int nseg) {
    extern __shared__ float sm[];
    float* qs = sm;
    float* ks = sm + ATTN_TILE;
    float* vs = sm + 2 * ATTN_TILE;
    float* ps = sm + 3 * ATTN_TILE;
    __shared__ int scuq[9], scuk[9];

    const int tid = threadIdx.x;
    const int qb = blockIdx.x, h = blockIdx.y, b = blockIdx.z;
    const int q0 = qb * 64;
    const int kvh = h / KVREP;
    const int row = tid >> 2, sub = tid & 3;

    if (tid <= nseg) { scuq[tid] = cu_q[tid]; scuk[tid] = cu_k[tid]; }

    const float* Qb = Q + ((size_t)(b * QLEN + q0)) * HIDDEN + h * HD;
    #pragma unroll
    for (int i = 0; i < 4; i++) {
        int idx = tid + 256 * i;
        int r = idx >> 4, q = (idx & 15) << 2;
        *reinterpret_cast<float4*>(qs + r * 68 + q) =
            *reinterpret_cast<const float4*>(Qb + (size_t)r * HIDDEN + q);
    }
    __syncthreads();

    const int qpos = q0 + row;
    int sq = 0;
    for (int s = 0; s < nseg - 1; s++) if (qpos >= scuq[s + 1]) sq++;
    int sqf = 0, sql = 0;
    for (int s = 0; s < nseg - 1; s++) {
        if (q0 >= scuq[s + 1]) sqf++;
        if (q0 + 63 >= scuq[s + 1]) sql++;
    }
    const int offset = KLEN - QLEN;  // 0 here, kept general
    int kend = min(KLEN, q0 + 63 + offset + 1);
    int kbeg = 0;
    if (sqf == sql) {  // whole q-block in one segment -> restrict kv range
        kbeg = scuk[sqf];
        kend = min(kend, scuk[sqf + 1]);
    }
    const int kb0 = (kbeg >> 6) << 6;

    float m = -INFINITY, l = 0.f;
    float o[16];
    #pragma unroll
    for (int j = 0; j < 16; j++) o[j] = 0.f;
    const float scale = rsqrtf((float)HD);

    for (int kb = kb0; kb < kend; kb += 64) {
        __syncthreads();
        const float* Kb = Kg + ((size_t)(b * KLEN + kb) * NKV + kvh) * HD;
        const float* Vb = Vg + ((size_t)(b * KLEN + kb) * NKV + kvh) * HD;
        #pragma unroll
        for (int i = 0; i < 4; i++) {
            int idx = tid + 256 * i;
            int r = idx >> 4, q = (idx & 15) << 2;
            *reinterpret_cast<float4*>(ks + r * 68 + q) =
                *reinterpret_cast<const float4*>(Kb + (size_t)r * (NKV * HD) + q);
            *reinterpret_cast<float4*>(vs + r * 68 + q) =
                *reinterpret_cast<const float4*>(Vb + (size_t)r * (NKV * HD) + q);
        }
        __syncthreads();

        float s[16];
        #pragma unroll
        for (int j = 0; j < 16; j++) s[j] = 0.f;
        #pragma unroll 8
        for (int d = 0; d < 64; d++) {
            float qv = qs[row * 68 + d];
            #pragma unroll
            for (int j = 0; j < 16; j++)
                s[j] += qv * ks[(4 * j + sub) * 68 + d];
        }
        #pragma unroll
        for (int j = 0; j < 16; j++) {
            int kpos = kb + 4 * j + sub;
            int sk = 0;
            for (int t = 0; t < nseg - 1; t++) if (kpos >= scuk[t + 1]) sk++;
            bool valid = (kpos <= qpos + offset) && (sk == sq);
            s[j] = valid ? s[j] * scale : -INFINITY;
        }
        float bm = -INFINITY;
        #pragma unroll
        for (int j = 0; j < 16; j++) bm = fmaxf(bm, s[j]);
        bm = fmaxf(bm, __shfl_xor_sync(0xffffffffu, bm, 1));
        bm = fmaxf(bm, __shfl_xor_sync(0xffffffffu, bm, 2));
        float mnew = fmaxf(m, bm);
        float msafe = (mnew == -INFINITY) ? 0.f : mnew;
        float corr = expf(m - msafe);  // m = -inf -> 0, first block safe
        float psum = 0.f;
        #pragma unroll
        for (int j = 0; j < 16; j++) {
            float p = expf(s[j] - msafe);  // masked -> exp(-inf) = 0
            ps[row * 68 + 4 * j + sub] = p;
            psum += p;
        }
        psum += __shfl_xor_sync(0xffffffffu, psum, 1);
        psum += __shfl_xor_sync(0xffffffffu, psum, 2);
        l = l * corr + psum;
        m = mnew;
        #pragma unroll
        for (int j = 0; j < 16; j++) o[j] *= corr;
        __syncwarp();
        #pragma unroll 8
        for (int k = 0; k < 64; k++) {
            float pv = ps[row * 68 + k];
            #pragma unroll
            for (int j = 0; j < 16; j++)
                o[j] += pv * vs[k * 68 + 4 * j + sub];
        }
        __syncwarp();
    }

    const float inv = (l > 0.f) ? 1.f / l : 0.f;
    float* Ob = O + ((size_t)(b * QLEN + q0 + row)) * HIDDEN + h * HD;
    #pragma unroll
    for (int j = 0; j < 16; j++) Ob[4 * j + sub] = o[j] * inv;
}

// ---------------- silu(gate) * up ----------------
__global__ void silu_mul_kernel(const float* __restrict__ g,
                                const float* __restrict__ u,
                                float* __restrict__ out, int n) {
    int i = blockIdx.x * blockDim.x + threadIdx.x;
    if (i < n) {
        float x = g[i];
        out[i] = (x / (1.f + expf(-x))) * u[i];
    }
}

// ---------------- launch ----------------
extern "C" void kernel_launch(void* const* d_in, const int* in_sizes, int n_in,
                              void* d_out, int out_size) {
    const float* hs   = (const float*)d_in[0];
    const float* kst  = (const float*)d_in[1];
    const float* vst  = (const float*)d_in[2];
    const float* wln1 = (const float*)d_in[4];
    const float* wln2 = (const float*)d_in[5];
    const float* wq   = (const float*)d_in[6];
    const float* wo   = (const float*)d_in[7];
    const float* wg   = (const float*)d_in[8];
    const float* wu   = (const float*)d_in[9];
    const float* wd   = (const float*)d_in[10];
    const int*   cuq  = (const int*)d_in[11];
    const int*   cuk  = (const int*)d_in[12];
    float* out = (float*)d_out;
    const int nseg = in_sizes[11] - 1;

    float *p_normed, *p_q, *p_attn, *p_h2, *p_normed2, *p_gate, *p_up;
    cudaGetSymbolAddress((void**)&p_normed,  g_normed);
    cudaGetSymbolAddress((void**)&p_q,       g_q);
    cudaGetSymbolAddress((void**)&p_attn,    g_attn);
    cudaGetSymbolAddress((void**)&p_h2,      g_h2);
    cudaGetSymbolAddress((void**)&p_normed2, g_normed2);
    cudaGetSymbolAddress((void**)&p_gate,    g_gate);
    cudaGetSymbolAddress((void**)&p_up,      g_up);

    cudaFuncSetAttribute(attn_kernel, cudaFuncAttributeMaxDynamicSharedMemorySize,
                         ATTN_SMEM);

    // 1. RMSNorm 1
    rmsnorm_kernel<<<MROWS, 256>>>(hs, wln1, p_normed);
    // 2. Q projection
    gemm_tf32<<<dim3(HIDDEN / 128, MROWS / 128), 256>>>(
        p_normed, wq, nullptr, p_q, MROWS, HIDDEN, HIDDEN);
    // 3. flash attention (segment + causal mask, GQA)
    attn_kernel<<<dim3(QLEN / 64, NHEADS, BATCH), 256, ATTN_SMEM>>>(
        p_q, kst, vst, p_attn, cuq, cuk, nseg);
    // 4. O projection + residual
    gemm_tf32<<<dim3(HIDDEN / 128, MROWS / 128), 256>>>(
        p_attn, wo, hs, p_h2, MROWS, HIDDEN, HIDDEN);
    // 5. RMSNorm 2
    rmsnorm_kernel<<<MROWS, 256>>>(p_h2, wln2, p_normed2);
    // 6/7. gate and up projections
    gemm_tf32<<<dim3(INTER / 128, MROWS / 128), 256>>>(
        p_normed2, wg, nullptr, p_gate, MROWS, INTER, HIDDEN);
    gemm_tf32<<<dim3(INTER / 128, MROWS / 128), 256>>>(
        p_normed2, wu, nullptr, p_up, MROWS, INTER, HIDDEN);
    // 8. silu(gate) * up  (in place into p_gate)
    silu_mul_kernel<<<(MROWS * (INTER / 256)), 256>>>(
        p_gate, p_up, p_gate, MROWS * INTER);
    // 9. down projection + residual -> d_out
    gemm_tf32<<<dim3(HIDDEN / 128, MROWS / 128), 256>>>(
        p_gate, wd, p_h2, out, MROWS, HIDDEN, INTER);
}

// round 5
// speedup vs baseline: 1.0862x; 1.0862x over previous
#include <cuda_runtime.h>
#include <cstdint>
#include <math.h>

// ---------------- problem constants ----------------
#define HIDDEN 2048
#define NHEADS 32
#define NKV    8
#define HD     64
#define KVREP  (NHEADS / NKV)
#define INTER  8192
#define BATCH  2
#define QLEN   2048
#define KLEN   2048
#define MROWS  (BATCH * QLEN)   // 4096

// ---------------- scratch (static device allocations) ----------------
__device__ float g_normed [(size_t)MROWS * HIDDEN];
__device__ float g_q      [(size_t)MROWS * HIDDEN];
__device__ float g_attn   [(size_t)MROWS * HIDDEN];
__device__ float g_h2     [(size_t)MROWS * HIDDEN];
__device__ float g_normed2[(size_t)MROWS * HIDDEN];
__device__ float g_gate   [(size_t)MROWS * INTER];
__device__ float g_up     [(size_t)MROWS * INTER];
// tf32-pre-rounded weight copies
__device__ float g_wq_r[(size_t)HIDDEN * HIDDEN];
__device__ float g_wo_r[(size_t)HIDDEN * HIDDEN];
__device__ float g_wg_r[(size_t)INTER * HIDDEN];
__device__ float g_wu_r[(size_t)INTER * HIDDEN];
__device__ float g_wd_r[(size_t)HIDDEN * INTER];

// ---------------- helpers ----------------
__device__ __forceinline__ float to_tf32(float x) {
    uint32_t u;
    asm("cvt.rna.tf32.f32 %0, %1;" : "=r"(u) : "f"(x));
    return __uint_as_float(u);
}

__device__ __forceinline__ void mma_tf32(float (&d)[4], const uint32_t (&a)[4],
                                         const uint32_t (&b)[2]) {
    asm volatile(
        "mma.sync.aligned.m16n8k8.row.col.f32.tf32.tf32.f32 "
        "{%0,%1,%2,%3}, {%4,%5,%6,%7}, {%8,%9}, {%0,%1,%2,%3};\n"
        : "+f"(d[0]), "+f"(d[1]), "+f"(d[2]), "+f"(d[3])
        : "r"(a[0]), "r"(a[1]), "r"(a[2]), "r"(a[3]), "r"(b[0]), "r"(b[1]));
}

// ---------------- weight pre-round (fp32 -> tf32 bits) ----------------
__global__ void round_w4(const float4* __restrict__ s, float4* __restrict__ d,
                         int n4) {
    int i = blockIdx.x * blockDim.x + threadIdx.x;
    int stride = gridDim.x * blockDim.x;
    for (; i < n4; i += stride) {
        float4 v = s[i];
        v.x = to_tf32(v.x); v.y = to_tf32(v.y);
        v.z = to_tf32(v.z); v.w = to_tf32(v.w);
        d[i] = v;
    }
}

// ---------------- RMSNorm (emits tf32-rounded output) ----------------
__global__ void rmsnorm_kernel(const float* __restrict__ x,
                               const float* __restrict__ w,
                               float* __restrict__ out) {
    const int row = blockIdx.x;
    const float* xr = x + (size_t)row * HIDDEN;
    float* orow = out + (size_t)row * HIDDEN;
    float s = 0.f;
    for (int i = threadIdx.x; i < HIDDEN; i += blockDim.x) {
        float v = xr[i];
        s += v * v;
    }
    __shared__ float red[32];
    #pragma unroll
    for (int o = 16; o; o >>= 1) s += __shfl_xor_sync(0xffffffffu, s, o);
    if ((threadIdx.x & 31) == 0) red[threadIdx.x >> 5] = s;
    __syncthreads();
    if (threadIdx.x < 32) {
        float v = (threadIdx.x < (blockDim.x >> 5)) ? red[threadIdx.x] : 0.f;
        #pragma unroll
        for (int o = 16; o; o >>= 1) v += __shfl_xor_sync(0xffffffffu, v, o);
        if (threadIdx.x == 0) red[0] = v;
    }
    __syncthreads();
    const float inv = rsqrtf(red[0] / (float)HIDDEN + 1e-5f);
    for (int i = threadIdx.x; i < HIDDEN; i += blockDim.x)
        orow[i] = to_tf32(xr[i] * inv * w[i]);
}

// ---------------- tf32 GEMM: C = A(M,K) @ B(N,K)^T (+ Res) ----------------
// CTA tile 128x128x32, 8 warps, 3-stage cp.async pipeline.
// Inputs must already be tf32-rounded (low 13 mantissa bits zero).
constexpr int GEMM_LDA = 36;                       // floats per smem row (pad)
constexpr int GEMM_STAGE_F = 2 * 128 * GEMM_LDA;   // A+B floats per stage
constexpr int GEMM_SMEM = 3 * GEMM_STAGE_F * (int)sizeof(float);  // 110592 B

__global__ void __launch_bounds__(256, 2) gemm_tf32(
    const float* __restrict__ A, const float* __restrict__ B,
    const float* __restrict__ Res, float* __restrict__ C,
    int M, int N, int K) {
    extern __shared__ float sm[];
    const int tid = threadIdx.x;
    const int warp = tid >> 5, lane = tid & 31;
    const int wm = warp >> 2, wn = warp & 3;
    const int gid = lane >> 2, tig = lane & 3;
    const int m0 = blockIdx.y * 128, n0 = blockIdx.x * 128;

    const float* Ag = A + (size_t)m0 * K;
    const float* Bg = B + (size_t)n0 * K;
    const uint32_t smem_u32 = (uint32_t)__cvta_generic_to_shared(sm);

    float acc[4][4][4];
    #pragma unroll
    for (int mt = 0; mt < 4; mt++)
        #pragma unroll
        for (int nt = 0; nt < 4; nt++)
            #pragma unroll
            for (int i = 0; i < 4; i++) acc[mt][nt][i] = 0.f;

    const int T = K >> 5;

    auto issue = [&](int tile, int st) {
        const uint32_t a_base = smem_u32 + (uint32_t)st * (GEMM_STAGE_F * 4);
        const uint32_t b_base = a_base + 128 * GEMM_LDA * 4;
        const int k0 = tile << 5;
        #pragma unroll
        for (int j = 0; j < 4; j++) {
            int c = tid + 256 * j;
            int r = c >> 3, q = (c & 7) << 2;
            uint32_t da = a_base + (uint32_t)(r * GEMM_LDA + q) * 4;
            const float* sa = Ag + (size_t)r * K + k0 + q;
            asm volatile("cp.async.cg.shared.global [%0], [%1], 16;"
                         :: "r"(da), "l"(sa));
            uint32_t db = b_base + (uint32_t)(r * GEMM_LDA + q) * 4;
            const float* sb = Bg + (size_t)r * K + k0 + q;
            asm volatile("cp.async.cg.shared.global [%0], [%1], 16;"
                         :: "r"(db), "l"(sb));
        }
        asm volatile("cp.async.commit_group;");
    };

    issue(0, 0);
    issue(1, 1);
    issue(2, 2);

    int st = 0;
    for (int i = 0; i < T; i++) {
        const int rem = T - 1 - i;
        if (rem >= 2)
            asm volatile("cp.async.wait_group 2;" ::: "memory");
        else if (rem == 1)
            asm volatile("cp.async.wait_group 1;" ::: "memory");
        else
            asm volatile("cp.async.wait_group 0;" ::: "memory");
        __syncthreads();

        const float* As = sm + st * GEMM_STAGE_F;
        const float* Bs = As + 128 * GEMM_LDA;
        #pragma unroll
        for (int ks = 0; ks < 32; ks += 8) {
            uint32_t af[4][4], bf[4][2];
            #pragma unroll
            for (int mt = 0; mt < 4; mt++) {
                const uint32_t* p = reinterpret_cast<const uint32_t*>(
                    As + (wm * 64 + mt * 16 + gid) * GEMM_LDA + ks + tig);
                af[mt][0] = p[0];
                af[mt][1] = p[8 * GEMM_LDA];
                af[mt][2] = p[4];
                af[mt][3] = p[8 * GEMM_LDA + 4];
            }
            #pragma unroll
            for (int nt = 0; nt < 4; nt++) {
                const uint32_t* p = reinterpret_cast<const uint32_t*>(
                    Bs + (wn * 32 + nt * 8 + gid) * GEMM_LDA + ks + tig);
                bf[nt][0] = p[0];
                bf[nt][1] = p[4];
            }
            #pragma unroll
            for (int mt = 0; mt < 4; mt++)
                #pragma unroll
                for (int nt = 0; nt < 4; nt++)
                    mma_tf32(acc[mt][nt], af[mt], bf[nt]);
        }
        __syncthreads();
        if (i + 3 < T) issue(i + 3, st);
        st = (st == 2) ? 0 : st + 1;
    }

    #pragma unroll
    for (int mt = 0; mt < 4; mt++) {
        int r = m0 + wm * 64 + mt * 16 + gid;
        #pragma unroll
        for (int nt = 0; nt < 4; nt++) {
            int c = n0 + wn * 32 + nt * 8 + tig * 2;
            size_t o0 = (size_t)r * N + c;
            size_t o1 = o0 + (size_t)8 * N;
            float2 v0 = make_float2(acc[mt][nt][0], acc[mt][nt][1]);
            float2 v1 = make_float2(acc[mt][nt][2], acc[mt][nt][3]);
            if (Res) {
                float2 r0 = *reinterpret_cast<const float2*>(Res + o0);
                float2 r1 = *reinterpret_cast<const float2*>(Res + o1);
                v0.x += r0.x; v0.y += r0.y;
                v1.x += r1.x; v1.y += r1.y;
            }
            *reinterpret_cast<float2*>(C + o0) = v0;
            *reinterpret_cast<float2*>(C + o1) = v1;
        }
    }
}

// ---------------- flash attention (fp32, 64x64 tiles) ----------------
constexpr int ATTN_TILE = 64 * 68;
constexpr int ATTN_SMEM = 4 * ATTN_TILE * (int)sizeof(float);  // 69632 B

__global__ void __launch_bounds__(256) attn_kernel(
    const float* __restrict__ Q, const float* __restrict__ Kg,
    const float* __restrict__ Vg, float* __restrict__ O,
    const int* __restrict__ cu_q, const int* __restrict__ cu_k, int nseg) {
    extern __shared__ float sm[];
    float* qs = sm;
    float* ks = sm + ATTN_TILE;
    float* vs = sm + 2 * ATTN_TILE;
    float* ps = sm + 3 * ATTN_TILE;
    __shared__ int scuq[9], scuk[9];

    const int tid = threadIdx.x;
    const int qb = blockIdx.x, h = blockIdx.y, b = blockIdx.z;
    const int q0 = qb * 64;
    const int kvh = h / KVREP;
    const int row = tid >> 2, sub = tid & 3;

    if (tid <= nseg) { scuq[tid] = cu_q[tid]; scuk[tid] = cu_k[tid]; }

    const float* Qb = Q + ((size_t)(b * QLEN + q0)) * HIDDEN + h * HD;
    #pragma unroll
    for (int i = 0; i < 4; i++) {
        int idx = tid + 256 * i;
        int r = idx >> 4, q = (idx & 15) << 2;
        *reinterpret_cast<float4*>(qs + r * 68 + q) =
            *reinterpret_cast<const float4*>(Qb + (size_t)r * HIDDEN + q);
    }
    __syncthreads();

    const int qpos = q0 + row;
    int sq = 0;
    for (int s = 0; s < nseg - 1; s++) if (qpos >= scuq[s + 1]) sq++;
    int sqf = 0, sql = 0;
    for (int s = 0; s < nseg - 1; s++) {
        if (q0 >= scuq[s + 1]) sqf++;
        if (q0 + 63 >= scuq[s + 1]) sql++;
    }
    const int offset = KLEN - QLEN;
    int kend = min(KLEN, q0 + 63 + offset + 1);
    int kbeg = 0;
    if (sqf == sql) {
        kbeg = scuk[sqf];
        kend = min(kend, scuk[sqf + 1]);
    }
    const int kb0 = (kbeg >> 6) << 6;

    float m = -INFINITY, l = 0.f;
    float o[16];
    #pragma unroll
    for (int j = 0; j < 16; j++) o[j] = 0.f;
    const float scale = rsqrtf((float)HD);

    for (int kb = kb0; kb < kend; kb += 64) {
        __syncthreads();
        const float* Kb = Kg + ((size_t)(b * KLEN + kb) * NKV + kvh) * HD;
        const float* Vb = Vg + ((size_t)(b * KLEN + kb) * NKV + kvh) * HD;
        #pragma unroll
        for (int i = 0; i < 4; i++) {
            int idx = tid + 256 * i;
            int r = idx >> 4, q = (idx & 15) << 2;
            *reinterpret_cast<float4*>(ks + r * 68 + q) =
                *reinterpret_cast<const float4*>(Kb + (size_t)r * (NKV * HD) + q);
            *reinterpret_cast<float4*>(vs + r * 68 + q) =
                *reinterpret_cast<const float4*>(Vb + (size_t)r * (NKV * HD) + q);
        }
        __syncthreads();

        float s[16];
        #pragma unroll
        for (int j = 0; j < 16; j++) s[j] = 0.f;
        #pragma unroll 8
        for (int d = 0; d < 64; d++) {
            float qv = qs[row * 68 + d];
            #pragma unroll
            for (int j = 0; j < 16; j++)
                s[j] += qv * ks[(4 * j + sub) * 68 + d];
        }
        #pragma unroll
        for (int j = 0; j < 16; j++) {
            int kpos = kb + 4 * j + sub;
            int sk = 0;
            for (int t = 0; t < nseg - 1; t++) if (kpos >= scuk[t + 1]) sk++;
            bool valid = (kpos <= qpos + offset) && (sk == sq);
            s[j] = valid ? s[j] * scale : -INFINITY;
        }
        float bm = -INFINITY;
        #pragma unroll
        for (int j = 0; j < 16; j++) bm = fmaxf(bm, s[j]);
        bm = fmaxf(bm, __shfl_xor_sync(0xffffffffu, bm, 1));
        bm = fmaxf(bm, __shfl_xor_sync(0xffffffffu, bm, 2));
        float mnew = fmaxf(m, bm);
        float msafe = (mnew == -INFINITY) ? 0.f : mnew;
        float corr = expf(m - msafe);
        float psum = 0.f;
        #pragma unroll
        for (int j = 0; j < 16; j++) {
            float p = expf(s[j] - msafe);
            ps[row * 68 + 4 * j + sub] = p;
            psum += p;
        }
        psum += __shfl_xor_sync(0xffffffffu, psum, 1);
        psum += __shfl_xor_sync(0xffffffffu, psum, 2);
        l = l * corr + psum;
        m = mnew;
        #pragma unroll
        for (int j = 0; j < 16; j++) o[j] *= corr;
        __syncwarp();
        #pragma unroll 8
        for (int k = 0; k < 64; k++) {
            float pv = ps[row * 68 + k];
            #pragma unroll
            for (int j = 0; j < 16; j++)
                o[j] += pv * vs[k * 68 + 4 * j + sub];
        }
        __syncwarp();
    }

    const float inv = (l > 0.f) ? 1.f / l : 0.f;
    float* Ob = O + ((size_t)(b * QLEN + q0 + row)) * HIDDEN + h * HD;
    #pragma unroll
    for (int j = 0; j < 16; j++) Ob[4 * j + sub] = to_tf32(o[j] * inv);
}

// ---------------- silu(gate) * up (emits tf32-rounded) ----------------
__global__ void silu_mul_kernel(const float* __restrict__ g,
                                const float* __restrict__ u,
                                float* __restrict__ out, int n) {
    int i = blockIdx.x * blockDim.x + threadIdx.x;
    if (i < n) {
        float x = g[i];
        out[i] = to_tf32((x / (1.f + expf(-x))) * u[i]);
    }
}

// ---------------- launch ----------------
extern "C" void kernel_launch(void* const* d_in, const int* in_sizes, int n_in,
                              void* d_out, int out_size) {
    const float* hs   = (const float*)d_in[0];
    const float* kst  = (const float*)d_in[1];
    const float* vst  = (const float*)d_in[2];
    const float* wln1 = (const float*)d_in[4];
    const float* wln2 = (const float*)d_in[5];
    const float* wq   = (const float*)d_in[6];
    const float* wo   = (const float*)d_in[7];
    const float* wg   = (const float*)d_in[8];
    const float* wu   = (const float*)d_in[9];
    const float* wd   = (const float*)d_in[10];
    const int*   cuq  = (const int*)d_in[11];
    const int*   cuk  = (const int*)d_in[12];
    float* out = (float*)d_out;
    const int nseg = in_sizes[11] - 1;

    float *p_normed, *p_q, *p_attn, *p_h2, *p_normed2, *p_gate, *p_up;
    float *p_wq, *p_wo, *p_wg, *p_wu, *p_wd;
    cudaGetSymbolAddress((void**)&p_normed,  g_normed);
    cudaGetSymbolAddress((void**)&p_q,       g_q);
    cudaGetSymbolAddress((void**)&p_attn,    g_attn);
    cudaGetSymbolAddress((void**)&p_h2,      g_h2);
    cudaGetSymbolAddress((void**)&p_normed2, g_normed2);
    cudaGetSymbolAddress((void**)&p_gate,    g_gate);
    cudaGetSymbolAddress((void**)&p_up,      g_up);
    cudaGetSymbolAddress((void**)&p_wq, g_wq_r);
    cudaGetSymbolAddress((void**)&p_wo, g_wo_r);
    cudaGetSymbolAddress((void**)&p_wg, g_wg_r);
    cudaGetSymbolAddress((void**)&p_wu, g_wu_r);
    cudaGetSymbolAddress((void**)&p_wd, g_wd_r);

    cudaFuncSetAttribute(attn_kernel, cudaFuncAttributeMaxDynamicSharedMemorySize,
                         ATTN_SMEM);
    cudaFuncSetAttribute(gemm_tf32, cudaFuncAttributeMaxDynamicSharedMemorySize,
                         GEMM_SMEM);

    // 0. pre-round weights to tf32 (once per replay; ~60us total)
    round_w4<<<1024, 256>>>((const float4*)wq, (float4*)p_wq,
                            (HIDDEN * HIDDEN) / 4);
    round_w4<<<1024, 256>>>((const float4*)wo, (float4*)p_wo,
                            (HIDDEN * HIDDEN) / 4);
    round_w4<<<2048, 256>>>((const float4*)wg, (float4*)p_wg,
                            (INTER * HIDDEN) / 4);
    round_w4<<<2048, 256>>>((const float4*)wu, (float4*)p_wu,
                            (INTER * HIDDEN) / 4);
    round_w4<<<2048, 256>>>((const float4*)wd, (float4*)p_wd,
                            (HIDDEN * INTER) / 4);

    // 1. RMSNorm 1 (tf32-rounded out)
    rmsnorm_kernel<<<MROWS, 256>>>(hs, wln1, p_normed);
    // 2. Q projection
    gemm_tf32<<<dim3(HIDDEN / 128, MROWS / 128), 256, GEMM_SMEM>>>(
        p_normed, p_wq, nullptr, p_q, MROWS, HIDDEN, HIDDEN);
    // 3. flash attention
    attn_kernel<<<dim3(QLEN / 64, NHEADS, BATCH), 256, ATTN_SMEM>>>(
        p_q, kst, vst, p_attn, cuq, cuk, nseg);
    // 4. O projection + residual
    gemm_tf32<<<dim3(HIDDEN / 128, MROWS / 128), 256, GEMM_SMEM>>>(
        p_attn, p_wo, hs, p_h2, MROWS, HIDDEN, HIDDEN);
    // 5. RMSNorm 2
    rmsnorm_kernel<<<MROWS, 256>>>(p_h2, wln2, p_normed2);
    // 6/7. gate and up projections
    gemm_tf32<<<dim3(INTER / 128, MROWS / 128), 256, GEMM_SMEM>>>(
        p_normed2, p_wg, nullptr, p_gate, MROWS, INTER, HIDDEN);
    gemm_tf32<<<dim3(INTER / 128, MROWS / 128), 256, GEMM_SMEM>>>(
        p_normed2, p_wu, nullptr, p_up, MROWS, INTER, HIDDEN);
    // 8. silu(gate) * up
    silu_mul_kernel<<<(MROWS * (INTER / 256)), 256>>>(
        p_gate, p_up, p_gate, MROWS * INTER);
    // 9. down projection + residual -> d_out
    gemm_tf32<<<dim3(HIDDEN / 128, MROWS / 128), 256, GEMM_SMEM>>>(
        p_gate, p_wd, p_h2, out, MROWS, HIDDEN, INTER);
}